// round 1
// baseline (speedup 1.0000x reference)
#include <cuda_runtime.h>
#include <cuda_bf16.h>
#include <cstdint>

// ---------------- problem constants ----------------
#define N_NODES   50000
#define N_EDGES   800000
#define IN_CH     256
#define HEADS     8
#define OUT_CH    32
#define HC        256          // HEADS*OUT_CH
#define NEG_SLOPE 0.2f

// ---------------- device scratch (no cudaMalloc allowed) ----------------
__device__ float g_Wh[(size_t)N_NODES * HC];          // 51.2 MB
__device__ float g_eL[N_NODES * HEADS];
__device__ float g_eR[N_NODES * HEADS];
__device__ float g_esum[N_NODES * HEADS];
__device__ int   g_deg[N_NODES];
__device__ int   g_ptr[N_NODES + 1];
__device__ int   g_cursor[N_NODES];
__device__ int   g_csr_src[N_EDGES];
__device__ float g_csr_w[(size_t)N_EDGES * HEADS];    // 25.6 MB
__device__ int   g_is64;

// ---------------- dtype detection (int64 vs int32 edge_index) ----------------
__global__ void detect_kernel(const int* ei_words) {
    if (threadIdx.x == 0) {
        int all0 = 1;
        for (int i = 0; i < 64; i++) {
            if (ei_words[2 * i + 1] != 0) { all0 = 0; break; }
        }
        g_is64 = all0;
    }
}

__device__ __forceinline__ int edge_val(const void* ei, long long idx, int is64) {
    if (is64) return (int)((const long long*)ei)[idx];
    return ((const int*)ei)[idx];
}

// ---------------- zero scratch ----------------
__global__ void zero_kernel() {
    int i = blockIdx.x * blockDim.x + threadIdx.x;
    if (i < N_NODES * HEADS) g_esum[i] = 0.0f;
    if (i < N_NODES)         g_deg[i]  = 0;
}

// ---------------- GEMM: Wh = x @ W^T  (M=50000, N=256, K=256) ----------------
#define BM 128
#define BN 128
#define BK 16

__global__ __launch_bounds__(256, 2)
void gemm_kernel(const float* __restrict__ x, const float* __restrict__ W) {
    __shared__ float As[BK][BM];
    __shared__ float Bs[BK][BN];

    const int t  = threadIdx.x;
    const int m0 = blockIdx.x * BM;
    const int n0 = blockIdx.y * BN;
    const int tx = t & 15;       // 0..15 -> 8 cols each
    const int ty = t >> 4;       // 0..15 -> 8 rows each
    const int r  = t >> 1;       // 0..127 (row within tile for loading)
    const int q  = t & 1;        // half of the 16 K-values

    float acc[8][8];
    #pragma unroll
    for (int i = 0; i < 8; i++)
        #pragma unroll
        for (int j = 0; j < 8; j++) acc[i][j] = 0.0f;

    for (int k0 = 0; k0 < IN_CH; k0 += BK) {
        // load A tile (x rows m0..m0+127, cols k0..k0+15), store transposed
        {
            int m = m0 + r;
            float4 v0, v1;
            if (m < N_NODES) {
                const float* p = x + (size_t)m * IN_CH + k0 + q * 8;
                v0 = *(const float4*)p;
                v1 = *(const float4*)(p + 4);
            } else {
                v0 = make_float4(0.f, 0.f, 0.f, 0.f);
                v1 = v0;
            }
            int kb = q * 8;
            As[kb + 0][r] = v0.x; As[kb + 1][r] = v0.y;
            As[kb + 2][r] = v0.z; As[kb + 3][r] = v0.w;
            As[kb + 4][r] = v1.x; As[kb + 5][r] = v1.y;
            As[kb + 6][r] = v1.z; As[kb + 7][r] = v1.w;

            // load B tile: W rows (n0+r), cols k0..k0+15, store transposed
            const float* pb = W + (size_t)(n0 + r) * IN_CH + k0 + q * 8;
            float4 b0 = *(const float4*)pb;
            float4 b1 = *(const float4*)(pb + 4);
            Bs[kb + 0][r] = b0.x; Bs[kb + 1][r] = b0.y;
            Bs[kb + 2][r] = b0.z; Bs[kb + 3][r] = b0.w;
            Bs[kb + 4][r] = b1.x; Bs[kb + 5][r] = b1.y;
            Bs[kb + 6][r] = b1.z; Bs[kb + 7][r] = b1.w;
        }
        __syncthreads();

        #pragma unroll
        for (int kk = 0; kk < BK; kk++) {
            float4 a0 = *(const float4*)&As[kk][ty * 8];
            float4 a1 = *(const float4*)&As[kk][ty * 8 + 4];
            float4 b0 = *(const float4*)&Bs[kk][tx * 8];
            float4 b1 = *(const float4*)&Bs[kk][tx * 8 + 4];
            float a[8] = {a0.x, a0.y, a0.z, a0.w, a1.x, a1.y, a1.z, a1.w};
            float b[8] = {b0.x, b0.y, b0.z, b0.w, b1.x, b1.y, b1.z, b1.w};
            #pragma unroll
            for (int i = 0; i < 8; i++)
                #pragma unroll
                for (int j = 0; j < 8; j++)
                    acc[i][j] = fmaf(a[i], b[j], acc[i][j]);
        }
        __syncthreads();
    }

    #pragma unroll
    for (int i = 0; i < 8; i++) {
        int m = m0 + ty * 8 + i;
        if (m < N_NODES) {
            float4 o0 = make_float4(acc[i][0], acc[i][1], acc[i][2], acc[i][3]);
            float4 o1 = make_float4(acc[i][4], acc[i][5], acc[i][6], acc[i][7]);
            float* dst = &g_Wh[(size_t)m * HC + n0 + tx * 8];
            *(float4*)dst       = o0;
            *(float4*)(dst + 4) = o1;
        }
    }
}

// ---------------- per-node attention halves: eL, eR ----------------
__global__ void elr_kernel(const float* __restrict__ aL, const float* __restrict__ aR) {
    int n = blockIdx.x;
    int t = threadIdx.x;               // 0..255, h = t/32 (warp == head)
    float wv = g_Wh[(size_t)n * HC + t];
    float pl = wv * aL[t];
    float pr = wv * aR[t];
    #pragma unroll
    for (int off = 16; off > 0; off >>= 1) {
        pl += __shfl_down_sync(0xffffffffu, pl, off);
        pr += __shfl_down_sync(0xffffffffu, pr, off);
    }
    if ((t & 31) == 0) {
        int h = t >> 5;
        g_eL[n * HEADS + h] = pl;
        g_eR[n * HEADS + h] = pr;
    }
}

// ---------------- degree count ----------------
__global__ void deg_kernel(const void* __restrict__ ei) {
    int e = blockIdx.x * blockDim.x + threadIdx.x;
    if (e >= N_EDGES) return;
    int is64 = g_is64;
    int dst = edge_val(ei, (long long)N_EDGES + e, is64);
    atomicAdd(&g_deg[dst], 1);
}

// ---------------- exclusive scan (single block) ----------------
__global__ void scan_kernel() {
    __shared__ int warp_sums[32];
    __shared__ int s_carry;
    int t = threadIdx.x;
    int lane = t & 31, wid = t >> 5;
    if (t == 0) { s_carry = 0; g_ptr[0] = 0; }
    __syncthreads();
    for (int base = 0; base < N_NODES; base += 1024) {
        int idx = base + t;
        int v = (idx < N_NODES) ? g_deg[idx] : 0;
        int incl = v;
        #pragma unroll
        for (int off = 1; off < 32; off <<= 1) {
            int nb = __shfl_up_sync(0xffffffffu, incl, off);
            if (lane >= off) incl += nb;
        }
        if (lane == 31) warp_sums[wid] = incl;
        __syncthreads();
        if (wid == 0) {
            int ws = warp_sums[lane];
            #pragma unroll
            for (int off = 1; off < 32; off <<= 1) {
                int nb = __shfl_up_sync(0xffffffffu, ws, off);
                if (lane >= off) ws += nb;
            }
            warp_sums[lane] = ws;
        }
        __syncthreads();
        int warp_off = (wid == 0) ? 0 : warp_sums[wid - 1];
        int carry = s_carry;
        int incl_total = carry + warp_off + incl;
        if (idx < N_NODES) {
            g_ptr[idx + 1]  = incl_total;
            g_cursor[idx]   = incl_total - v;   // exclusive = start offset
        }
        __syncthreads();
        if (t == 1023) s_carry = incl_total;
        __syncthreads();
    }
}

// ---------------- edge scatter: weights + denominators + CSR fill ----------------
__global__ void scatter_kernel(const void* __restrict__ ei) {
    int e = blockIdx.x * blockDim.x + threadIdx.x;
    if (e >= N_EDGES) return;
    int is64 = g_is64;
    int src = edge_val(ei, e, is64);
    int dst = edge_val(ei, (long long)N_EDGES + e, is64);

    float4 l0 = *(const float4*)&g_eL[src * HEADS];
    float4 l1 = *(const float4*)&g_eL[src * HEADS + 4];
    float4 r0 = *(const float4*)&g_eR[dst * HEADS];
    float4 r1 = *(const float4*)&g_eR[dst * HEADS + 4];

    float s[8];
    s[0] = l0.x + r0.x; s[1] = l0.y + r0.y; s[2] = l0.z + r0.z; s[3] = l0.w + r0.w;
    s[4] = l1.x + r1.x; s[5] = l1.y + r1.y; s[6] = l1.z + r1.z; s[7] = l1.w + r1.w;

    float w[8];
    #pragma unroll
    for (int h = 0; h < 8; h++) {
        float v = fmaxf(s[h], NEG_SLOPE * s[h]);   // leaky relu
        w[h] = __expf(v);                           // no max-shift needed (|e| small)
        atomicAdd(&g_esum[dst * HEADS + h], w[h]);
    }

    int pos = atomicAdd(&g_cursor[dst], 1);
    g_csr_src[pos] = src;
    float* cw = &g_csr_w[(size_t)pos * HEADS];
    *(float4*)cw       = make_float4(w[0], w[1], w[2], w[3]);
    *(float4*)(cw + 4) = make_float4(w[4], w[5], w[6], w[7]);
}

// ---------------- aggregation: one block per dst node ----------------
__global__ __launch_bounds__(256)
void agg_kernel(float* __restrict__ out) {
    int n = blockIdx.x;
    int t = threadIdx.x;       // channel
    int h = t >> 5;

    float el = g_eL[n * HEADS + h];
    float er = g_eR[n * HEADS + h];
    float ss = el + er;
    ss = fmaxf(ss, NEG_SLOPE * ss);
    float wself = __expf(ss);

    float acc = wself * g_Wh[(size_t)n * HC + t];

    int beg = g_ptr[n];
    int end = g_ptr[n + 1];
    for (int k = beg; k < end; k++) {
        int src  = g_csr_src[k];
        float w  = g_csr_w[(size_t)k * HEADS + h];
        acc = fmaf(w, g_Wh[(size_t)src * HC + t], acc);
    }

    float denom = g_esum[n * HEADS + h] + wself + 1e-16f;
    out[(size_t)n * HC + t] = acc / denom;
}

// ---------------- launch ----------------
extern "C" void kernel_launch(void* const* d_in, const int* in_sizes, int n_in,
                              void* d_out, int out_size) {
    const float* x  = (const float*)d_in[0];
    const void*  ei = d_in[1];
    const float* W  = (const float*)d_in[2];
    const float* aL = (const float*)d_in[3];
    const float* aR = (const float*)d_in[4];
    float* out = (float*)d_out;

    detect_kernel<<<1, 32>>>((const int*)ei);
    zero_kernel<<<(N_NODES * HEADS + 255) / 256, 256>>>();

    dim3 ggrid((N_NODES + BM - 1) / BM, HC / BN);
    gemm_kernel<<<ggrid, 256>>>(x, W);

    elr_kernel<<<N_NODES, 256>>>(aL, aR);
    deg_kernel<<<(N_EDGES + 255) / 256, 256>>>(ei);
    scan_kernel<<<1, 1024>>>();
    scatter_kernel<<<(N_EDGES + 255) / 256, 256>>>(ei);
    agg_kernel<<<N_NODES, 256>>>(out);
}

// round 2
// speedup vs baseline: 1.5366x; 1.5366x over previous
#include <cuda_runtime.h>
#include <cuda_bf16.h>
#include <cstdint>

// ---------------- problem constants ----------------
#define N_NODES   50000
#define N_EDGES   800000
#define IN_CH     256
#define HEADS     8
#define OUT_CH    32
#define HC        256          // HEADS*OUT_CH
#define NEG_SLOPE 0.2f

// ---------------- device scratch ----------------
__device__ float g_Wh[(size_t)N_NODES * HC];          // 51.2 MB
__device__ float g_eL[N_NODES * HEADS];
__device__ float g_eR[N_NODES * HEADS];
__device__ int   g_deg[N_NODES];
__device__ int   g_ptr[N_NODES + 1];
__device__ int   g_cursor[N_NODES];
__device__ int   g_csr_src[N_EDGES];
__device__ int   g_is64;

// ---------------- dtype detection (int64 vs int32 edge_index) ----------------
__global__ void detect_kernel(const int* ei_words) {
    if (threadIdx.x == 0) {
        int all0 = 1;
        for (int i = 0; i < 64; i++) {
            if (ei_words[2 * i + 1] != 0) { all0 = 0; break; }
        }
        g_is64 = all0;
    }
}

__device__ __forceinline__ int edge_val(const void* ei, long long idx, int is64) {
    if (is64) return (int)((const long long*)ei)[idx];
    return ((const int*)ei)[idx];
}

__global__ void zero_kernel() {
    int i = blockIdx.x * blockDim.x + threadIdx.x;
    if (i < N_NODES) g_deg[i] = 0;
}

// ---------------- bf16 split helper ----------------
__device__ __forceinline__ uint32_t pack_split(float x0, float x1, uint32_t& lo_out) {
    __nv_bfloat16 h0 = __float2bfloat16_rn(x0);
    __nv_bfloat16 h1 = __float2bfloat16_rn(x1);
    __nv_bfloat16 l0 = __float2bfloat16_rn(x0 - __bfloat162float(h0));
    __nv_bfloat16 l1 = __float2bfloat16_rn(x1 - __bfloat162float(h1));
    lo_out = (uint32_t)__bfloat16_as_ushort(l0) | ((uint32_t)__bfloat16_as_ushort(l1) << 16);
    return (uint32_t)__bfloat16_as_ushort(h0) | ((uint32_t)__bfloat16_as_ushort(h1) << 16);
}

__device__ __forceinline__ void mma_bf16(float* c, const uint32_t* a, const uint32_t* b) {
    asm volatile(
        "mma.sync.aligned.m16n8k16.row.col.f32.bf16.bf16.f32 "
        "{%0,%1,%2,%3}, {%4,%5,%6,%7}, {%8,%9}, {%0,%1,%2,%3};\n"
        : "+f"(c[0]), "+f"(c[1]), "+f"(c[2]), "+f"(c[3])
        : "r"(a[0]), "r"(a[1]), "r"(a[2]), "r"(a[3]), "r"(b[0]), "r"(b[1]));
}

// ---------------- GEMM: Wh = x @ W^T  (tensor cores, bf16x3 split) --------
// Tile: BM=128, BN=64, BK=32. 8 warps (4x2). Warp tile 32x32 = one head wide.
// Fused epilogue computes eL/eR per (node, head).
#define SA 20   // smem row stride in bf16-pairs (40 bf16 = 80B, conflict-free)

__global__ __launch_bounds__(256, 2)
void gemm_kernel(const float* __restrict__ x, const float* __restrict__ W,
                 const float* __restrict__ aL, const float* __restrict__ aR) {
    __shared__ uint32_t Ah[128 * SA], Al[128 * SA];
    __shared__ uint32_t Bh[64 * SA],  Bl[64 * SA];

    const int t    = threadIdx.x;
    const int m0   = blockIdx.x * 128;
    const int n0   = blockIdx.y * 64;
    const int wid  = t >> 5, lane = t & 31;
    const int wm   = wid & 3, wn = wid >> 2;
    const int g    = lane >> 2, tt = lane & 3;

    // global load assignments
    const int ar = t >> 1;             // A row 0..127
    const int ak = (t & 1) * 16;       // A k-half
    const int br = t >> 2;             // B row 0..63
    const int bk = (t & 3) * 8;        // B k-quarter

    float c[2][4][4];
    #pragma unroll
    for (int i = 0; i < 2; i++)
        #pragma unroll
        for (int j = 0; j < 4; j++)
            #pragma unroll
            for (int k = 0; k < 4; k++) c[i][j][k] = 0.0f;

    float4 a_reg[4];
    float4 b_reg[2];

    auto loadA = [&](int k0) {
        int m = m0 + ar;
        if (m < N_NODES) {
            const float4* p = (const float4*)(x + (size_t)m * IN_CH + k0 + ak);
            a_reg[0] = p[0]; a_reg[1] = p[1]; a_reg[2] = p[2]; a_reg[3] = p[3];
        } else {
            a_reg[0] = a_reg[1] = a_reg[2] = a_reg[3] = make_float4(0.f, 0.f, 0.f, 0.f);
        }
        const float4* q = (const float4*)(W + (size_t)(n0 + br) * IN_CH + k0 + bk);
        b_reg[0] = q[0]; b_reg[1] = q[1];
    };

    loadA(0);

    for (int k0 = 0; k0 < IN_CH; k0 += 32) {
        // convert + STS from registers
        {
            float av[16] = {a_reg[0].x, a_reg[0].y, a_reg[0].z, a_reg[0].w,
                            a_reg[1].x, a_reg[1].y, a_reg[1].z, a_reg[1].w,
                            a_reg[2].x, a_reg[2].y, a_reg[2].z, a_reg[2].w,
                            a_reg[3].x, a_reg[3].y, a_reg[3].z, a_reg[3].w};
            #pragma unroll
            for (int i = 0; i < 8; i++) {
                uint32_t lo;
                uint32_t hi = pack_split(av[2 * i], av[2 * i + 1], lo);
                Ah[ar * SA + ak / 2 + i] = hi;
                Al[ar * SA + ak / 2 + i] = lo;
            }
            float bv[8] = {b_reg[0].x, b_reg[0].y, b_reg[0].z, b_reg[0].w,
                           b_reg[1].x, b_reg[1].y, b_reg[1].z, b_reg[1].w};
            #pragma unroll
            for (int i = 0; i < 4; i++) {
                uint32_t lo;
                uint32_t hi = pack_split(bv[2 * i], bv[2 * i + 1], lo);
                Bh[br * SA + bk / 2 + i] = hi;
                Bl[br * SA + bk / 2 + i] = lo;
            }
        }
        __syncthreads();

        if (k0 + 32 < IN_CH) loadA(k0 + 32);   // prefetch overlaps compute

        #pragma unroll
        for (int ks = 0; ks < 2; ks++) {
            const int kb2 = ks * 8;  // pair offset of this k16 step
            uint32_t bhf[4][2], blf[4][2];
            #pragma unroll
            for (int fn = 0; fn < 4; fn++) {
                int nrow = wn * 32 + fn * 8 + g;
                bhf[fn][0] = Bh[nrow * SA + kb2 + tt];
                bhf[fn][1] = Bh[nrow * SA + kb2 + 4 + tt];
                blf[fn][0] = Bl[nrow * SA + kb2 + tt];
                blf[fn][1] = Bl[nrow * SA + kb2 + 4 + tt];
            }
            #pragma unroll
            for (int fm = 0; fm < 2; fm++) {
                int r0 = wm * 32 + fm * 16 + g;
                uint32_t ahf[4], alf[4];
                ahf[0] = Ah[r0 * SA + kb2 + tt];
                ahf[1] = Ah[(r0 + 8) * SA + kb2 + tt];
                ahf[2] = Ah[r0 * SA + kb2 + 4 + tt];
                ahf[3] = Ah[(r0 + 8) * SA + kb2 + 4 + tt];
                alf[0] = Al[r0 * SA + kb2 + tt];
                alf[1] = Al[(r0 + 8) * SA + kb2 + tt];
                alf[2] = Al[r0 * SA + kb2 + 4 + tt];
                alf[3] = Al[(r0 + 8) * SA + kb2 + 4 + tt];
                #pragma unroll
                for (int fn = 0; fn < 4; fn++) {
                    mma_bf16(c[fm][fn], ahf, bhf[fn]);   // hi*hi
                    mma_bf16(c[fm][fn], ahf, blf[fn]);   // hi*lo
                    mma_bf16(c[fm][fn], alf, bhf[fn]);   // lo*hi
                }
            }
        }
        __syncthreads();
    }

    // ---- epilogue: store Wh + fused eL/eR ----
    const int h = blockIdx.y * 2 + wn;   // global head for this warp
    float aLv[8], aRv[8];
    #pragma unroll
    for (int fn = 0; fn < 4; fn++) {
        int c0 = fn * 8 + 2 * tt;
        aLv[2 * fn]     = aL[h * 32 + c0];
        aLv[2 * fn + 1] = aL[h * 32 + c0 + 1];
        aRv[2 * fn]     = aR[h * 32 + c0];
        aRv[2 * fn + 1] = aR[h * 32 + c0 + 1];
    }

    #pragma unroll
    for (int fm = 0; fm < 2; fm++) {
        int mrow = m0 + wm * 32 + fm * 16 + g;
        #pragma unroll
        for (int fn = 0; fn < 4; fn++) {
            int col = n0 + wn * 32 + fn * 8 + 2 * tt;
            if (mrow < N_NODES)
                *(float2*)&g_Wh[(size_t)mrow * HC + col] =
                    make_float2(c[fm][fn][0], c[fm][fn][1]);
            if (mrow + 8 < N_NODES)
                *(float2*)&g_Wh[(size_t)(mrow + 8) * HC + col] =
                    make_float2(c[fm][fn][2], c[fm][fn][3]);
        }
        #pragma unroll
        for (int half = 0; half < 2; half++) {
            float pl = 0.f, pr = 0.f;
            #pragma unroll
            for (int fn = 0; fn < 4; fn++) {
                pl += c[fm][fn][2 * half] * aLv[2 * fn] + c[fm][fn][2 * half + 1] * aLv[2 * fn + 1];
                pr += c[fm][fn][2 * half] * aRv[2 * fn] + c[fm][fn][2 * half + 1] * aRv[2 * fn + 1];
            }
            pl += __shfl_xor_sync(0xffffffffu, pl, 1);
            pl += __shfl_xor_sync(0xffffffffu, pl, 2);
            pr += __shfl_xor_sync(0xffffffffu, pr, 1);
            pr += __shfl_xor_sync(0xffffffffu, pr, 2);
            int m = mrow + half * 8;
            if (tt == 0 && m < N_NODES) {
                g_eL[m * HEADS + h] = pl;
                g_eR[m * HEADS + h] = pr;
            }
        }
    }
}

// ---------------- degree count ----------------
__global__ void deg_kernel(const void* __restrict__ ei) {
    int e = blockIdx.x * blockDim.x + threadIdx.x;
    if (e >= N_EDGES) return;
    int dst = edge_val(ei, (long long)N_EDGES + e, g_is64);
    atomicAdd(&g_deg[dst], 1);
}

// ---------------- exclusive scan (single block) ----------------
__global__ void scan_kernel() {
    __shared__ int warp_sums[32];
    __shared__ int s_carry;
    int t = threadIdx.x;
    int lane = t & 31, wid = t >> 5;
    if (t == 0) { s_carry = 0; g_ptr[0] = 0; }
    __syncthreads();
    for (int base = 0; base < N_NODES; base += 1024) {
        int idx = base + t;
        int v = (idx < N_NODES) ? g_deg[idx] : 0;
        int incl = v;
        #pragma unroll
        for (int off = 1; off < 32; off <<= 1) {
            int nb = __shfl_up_sync(0xffffffffu, incl, off);
            if (lane >= off) incl += nb;
        }
        if (lane == 31) warp_sums[wid] = incl;
        __syncthreads();
        if (wid == 0) {
            int ws = warp_sums[lane];
            #pragma unroll
            for (int off = 1; off < 32; off <<= 1) {
                int nb = __shfl_up_sync(0xffffffffu, ws, off);
                if (lane >= off) ws += nb;
            }
            warp_sums[lane] = ws;
        }
        __syncthreads();
        int warp_off = (wid == 0) ? 0 : warp_sums[wid - 1];
        int carry = s_carry;
        int incl_total = carry + warp_off + incl;
        if (idx < N_NODES) {
            g_ptr[idx + 1] = incl_total;
            g_cursor[idx]  = incl_total - v;
        }
        __syncthreads();
        if (t == 1023) s_carry = incl_total;
        __syncthreads();
    }
}

// ---------------- CSR fill (src only — weights recomputed in agg) --------
__global__ void scatter_kernel(const void* __restrict__ ei) {
    int e = blockIdx.x * blockDim.x + threadIdx.x;
    if (e >= N_EDGES) return;
    int is64 = g_is64;
    int src = edge_val(ei, e, is64);
    int dst = edge_val(ei, (long long)N_EDGES + e, is64);
    int pos = atomicAdd(&g_cursor[dst], 1);
    g_csr_src[pos] = src;
}

// ---------------- aggregation: one block per dst node ----------------
__global__ __launch_bounds__(256)
void agg_kernel(float* __restrict__ out) {
    __shared__ float s_w[32][8];
    __shared__ int   s_src[32];

    int n = blockIdx.x;
    int t = threadIdx.x;       // channel
    int h = t >> 5;

    float ss = g_eL[n * HEADS + h] + g_eR[n * HEADS + h];
    ss = fmaxf(ss, NEG_SLOPE * ss);
    float wself = __expf(ss);

    float acc   = wself * g_Wh[(size_t)n * HC + t];
    float denom = wself;

    int beg = g_ptr[n];
    int end = g_ptr[n + 1];

    int eh   = t & 7;          // head handled in phase 1
    int eidx = t >> 3;         // edge slot handled in phase 1
    float er_h = g_eR[n * HEADS + eh];

    for (int base = beg; base < end; base += 32) {
        int cnt = min(32, end - base);
        __syncthreads();
        if (eidx < cnt) {
            int src = g_csr_src[base + eidx];
            s_src[eidx] = src;
            float s = g_eL[src * HEADS + eh] + er_h;
            s = fmaxf(s, NEG_SLOPE * s);
            s_w[eidx][eh] = __expf(s);
        }
        __syncthreads();
        for (int k = 0; k < cnt; k++) {
            int src = s_src[k];
            float w = s_w[k][h];
            acc   = fmaf(w, g_Wh[(size_t)src * HC + t], acc);
            denom += w;
        }
    }
    out[(size_t)n * HC + t] = acc / (denom + 1e-16f);
}

// ---------------- launch ----------------
extern "C" void kernel_launch(void* const* d_in, const int* in_sizes, int n_in,
                              void* d_out, int out_size) {
    const float* x  = (const float*)d_in[0];
    const void*  ei = d_in[1];
    const float* W  = (const float*)d_in[2];
    const float* aL = (const float*)d_in[3];
    const float* aR = (const float*)d_in[4];
    float* out = (float*)d_out;

    detect_kernel<<<1, 32>>>((const int*)ei);
    zero_kernel<<<(N_NODES + 255) / 256, 256>>>();

    dim3 ggrid((N_NODES + 127) / 128, HC / 64);
    gemm_kernel<<<ggrid, 256>>>(x, W, aL, aR);

    deg_kernel<<<(N_EDGES + 255) / 256, 256>>>(ei);
    scan_kernel<<<1, 1024>>>();
    scatter_kernel<<<(N_EDGES + 255) / 256, 256>>>(ei);
    agg_kernel<<<N_NODES, 256>>>(out);
}

// round 3
// speedup vs baseline: 1.5980x; 1.0399x over previous
#include <cuda_runtime.h>
#include <cuda_bf16.h>
#include <cuda_fp16.h>
#include <cstdint>

// ---------------- problem constants ----------------
#define N_NODES   50000
#define N_EDGES   800000
#define IN_CH     256
#define HEADS     8
#define OUT_CH    32
#define HC        256          // HEADS*OUT_CH
#define NEG_SLOPE 0.2f

// ---------------- device scratch ----------------
__device__ __half2 g_Whh[(size_t)N_NODES * (HC / 2)];   // 25.6 MB, fp16 Wh
__device__ float g_eL[N_NODES * HEADS];
__device__ float g_eR[N_NODES * HEADS];
__device__ int   g_deg[N_NODES];
__device__ int   g_ptr[N_NODES + 1];
__device__ int   g_cursor[N_NODES];
__device__ int   g_csr_src[N_EDGES];
__device__ int   g_is64;

// ---------------- init: dtype detect + zero deg ----------------
__global__ void init_kernel(const int* ei_words) {
    int i = blockIdx.x * blockDim.x + threadIdx.x;
    if (i == 0) {
        int all0 = 1;
        for (int k = 0; k < 64; k++) {
            if (ei_words[2 * k + 1] != 0) { all0 = 0; break; }
        }
        g_is64 = all0;
    }
    if (i < N_NODES) g_deg[i] = 0;
}

// ---------------- bf16 split helper ----------------
__device__ __forceinline__ uint32_t pack_split(float x0, float x1, uint32_t& lo_out) {
    __nv_bfloat16 h0 = __float2bfloat16_rn(x0);
    __nv_bfloat16 h1 = __float2bfloat16_rn(x1);
    __nv_bfloat16 l0 = __float2bfloat16_rn(x0 - __bfloat162float(h0));
    __nv_bfloat16 l1 = __float2bfloat16_rn(x1 - __bfloat162float(h1));
    lo_out = (uint32_t)__bfloat16_as_ushort(l0) | ((uint32_t)__bfloat16_as_ushort(l1) << 16);
    return (uint32_t)__bfloat16_as_ushort(h0) | ((uint32_t)__bfloat16_as_ushort(h1) << 16);
}

__device__ __forceinline__ void mma_bf16(float* c, const uint32_t* a, const uint32_t* b) {
    asm volatile(
        "mma.sync.aligned.m16n8k16.row.col.f32.bf16.bf16.f32 "
        "{%0,%1,%2,%3}, {%4,%5,%6,%7}, {%8,%9}, {%0,%1,%2,%3};\n"
        : "+f"(c[0]), "+f"(c[1]), "+f"(c[2]), "+f"(c[3])
        : "r"(a[0]), "r"(a[1]), "r"(a[2]), "r"(a[3]), "r"(b[0]), "r"(b[1]));
}

// ---------------- GEMM: Wh = x @ W^T  (tensor cores, bf16x3 split) --------
// Tile: BM=128, BN=64, BK=32. 8 warps (4x2). Warp tile 32x32 = one head wide.
// Fused epilogue computes eL/eR and stores Wh as fp16.
#define SA 20   // smem row stride in bf16-pairs

__global__ __launch_bounds__(256, 2)
void gemm_kernel(const float* __restrict__ x, const float* __restrict__ W,
                 const float* __restrict__ aL, const float* __restrict__ aR) {
    __shared__ uint32_t Ah[128 * SA], Al[128 * SA];
    __shared__ uint32_t Bh[64 * SA],  Bl[64 * SA];

    const int t    = threadIdx.x;
    const int m0   = blockIdx.x * 128;
    const int n0   = blockIdx.y * 64;
    const int wid  = t >> 5, lane = t & 31;
    const int wm   = wid & 3, wn = wid >> 2;
    const int g    = lane >> 2, tt = lane & 3;

    const int ar = t >> 1;             // A row 0..127
    const int ak = (t & 1) * 16;       // A k-half
    const int br = t >> 2;             // B row 0..63
    const int bk = (t & 3) * 8;        // B k-quarter

    float c[2][4][4];
    #pragma unroll
    for (int i = 0; i < 2; i++)
        #pragma unroll
        for (int j = 0; j < 4; j++)
            #pragma unroll
            for (int k = 0; k < 4; k++) c[i][j][k] = 0.0f;

    float4 a_reg[4];
    float4 b_reg[2];

    auto loadA = [&](int k0) {
        int m = m0 + ar;
        if (m < N_NODES) {
            const float4* p = (const float4*)(x + (size_t)m * IN_CH + k0 + ak);
            a_reg[0] = p[0]; a_reg[1] = p[1]; a_reg[2] = p[2]; a_reg[3] = p[3];
        } else {
            a_reg[0] = a_reg[1] = a_reg[2] = a_reg[3] = make_float4(0.f, 0.f, 0.f, 0.f);
        }
        const float4* q = (const float4*)(W + (size_t)(n0 + br) * IN_CH + k0 + bk);
        b_reg[0] = q[0]; b_reg[1] = q[1];
    };

    loadA(0);

    for (int k0 = 0; k0 < IN_CH; k0 += 32) {
        {
            float av[16] = {a_reg[0].x, a_reg[0].y, a_reg[0].z, a_reg[0].w,
                            a_reg[1].x, a_reg[1].y, a_reg[1].z, a_reg[1].w,
                            a_reg[2].x, a_reg[2].y, a_reg[2].z, a_reg[2].w,
                            a_reg[3].x, a_reg[3].y, a_reg[3].z, a_reg[3].w};
            #pragma unroll
            for (int i = 0; i < 8; i++) {
                uint32_t lo;
                uint32_t hi = pack_split(av[2 * i], av[2 * i + 1], lo);
                Ah[ar * SA + ak / 2 + i] = hi;
                Al[ar * SA + ak / 2 + i] = lo;
            }
            float bv[8] = {b_reg[0].x, b_reg[0].y, b_reg[0].z, b_reg[0].w,
                           b_reg[1].x, b_reg[1].y, b_reg[1].z, b_reg[1].w};
            #pragma unroll
            for (int i = 0; i < 4; i++) {
                uint32_t lo;
                uint32_t hi = pack_split(bv[2 * i], bv[2 * i + 1], lo);
                Bh[br * SA + bk / 2 + i] = hi;
                Bl[br * SA + bk / 2 + i] = lo;
            }
        }
        __syncthreads();

        if (k0 + 32 < IN_CH) loadA(k0 + 32);

        #pragma unroll
        for (int ks = 0; ks < 2; ks++) {
            const int kb2 = ks * 8;
            uint32_t bhf[4][2], blf[4][2];
            #pragma unroll
            for (int fn = 0; fn < 4; fn++) {
                int nrow = wn * 32 + fn * 8 + g;
                bhf[fn][0] = Bh[nrow * SA + kb2 + tt];
                bhf[fn][1] = Bh[nrow * SA + kb2 + 4 + tt];
                blf[fn][0] = Bl[nrow * SA + kb2 + tt];
                blf[fn][1] = Bl[nrow * SA + kb2 + 4 + tt];
            }
            #pragma unroll
            for (int fm = 0; fm < 2; fm++) {
                int r0 = wm * 32 + fm * 16 + g;
                uint32_t ahf[4], alf[4];
                ahf[0] = Ah[r0 * SA + kb2 + tt];
                ahf[1] = Ah[(r0 + 8) * SA + kb2 + tt];
                ahf[2] = Ah[r0 * SA + kb2 + 4 + tt];
                ahf[3] = Ah[(r0 + 8) * SA + kb2 + 4 + tt];
                alf[0] = Al[r0 * SA + kb2 + tt];
                alf[1] = Al[(r0 + 8) * SA + kb2 + tt];
                alf[2] = Al[r0 * SA + kb2 + 4 + tt];
                alf[3] = Al[(r0 + 8) * SA + kb2 + 4 + tt];
                #pragma unroll
                for (int fn = 0; fn < 4; fn++) {
                    mma_bf16(c[fm][fn], ahf, bhf[fn]);   // hi*hi
                    mma_bf16(c[fm][fn], ahf, blf[fn]);   // hi*lo
                    mma_bf16(c[fm][fn], alf, bhf[fn]);   // lo*hi
                }
            }
        }
        __syncthreads();
    }

    // ---- epilogue: store fp16 Wh + fused eL/eR ----
    const int h = blockIdx.y * 2 + wn;
    float aLv[8], aRv[8];
    #pragma unroll
    for (int fn = 0; fn < 4; fn++) {
        int c0 = fn * 8 + 2 * tt;
        aLv[2 * fn]     = aL[h * 32 + c0];
        aLv[2 * fn + 1] = aL[h * 32 + c0 + 1];
        aRv[2 * fn]     = aR[h * 32 + c0];
        aRv[2 * fn + 1] = aR[h * 32 + c0 + 1];
    }

    #pragma unroll
    for (int fm = 0; fm < 2; fm++) {
        int mrow = m0 + wm * 32 + fm * 16 + g;
        #pragma unroll
        for (int fn = 0; fn < 4; fn++) {
            int colp = (n0 + wn * 32 + fn * 8 + 2 * tt) >> 1;  // half2 index
            if (mrow < N_NODES)
                g_Whh[(size_t)mrow * (HC / 2) + colp] =
                    __floats2half2_rn(c[fm][fn][0], c[fm][fn][1]);
            if (mrow + 8 < N_NODES)
                g_Whh[(size_t)(mrow + 8) * (HC / 2) + colp] =
                    __floats2half2_rn(c[fm][fn][2], c[fm][fn][3]);
        }
        #pragma unroll
        for (int half = 0; half < 2; half++) {
            float pl = 0.f, pr = 0.f;
            #pragma unroll
            for (int fn = 0; fn < 4; fn++) {
                pl += c[fm][fn][2 * half] * aLv[2 * fn] + c[fm][fn][2 * half + 1] * aLv[2 * fn + 1];
                pr += c[fm][fn][2 * half] * aRv[2 * fn] + c[fm][fn][2 * half + 1] * aRv[2 * fn + 1];
            }
            pl += __shfl_xor_sync(0xffffffffu, pl, 1);
            pl += __shfl_xor_sync(0xffffffffu, pl, 2);
            pr += __shfl_xor_sync(0xffffffffu, pr, 1);
            pr += __shfl_xor_sync(0xffffffffu, pr, 2);
            int m = mrow + half * 8;
            if (tt == 0 && m < N_NODES) {
                g_eL[m * HEADS + h] = pl;
                g_eR[m * HEADS + h] = pr;
            }
        }
    }
}

// ---------------- degree count: 4 edges / thread ----------------
__global__ void deg_kernel(const void* __restrict__ ei) {
    int e4 = blockIdx.x * blockDim.x + threadIdx.x;
    if (e4 * 4 >= N_EDGES) return;
    int d[4];
    if (g_is64) {
        const longlong2* p = (const longlong2*)((const long long*)ei + N_EDGES) + e4 * 2;
        longlong2 v0 = p[0], v1 = p[1];
        d[0] = (int)v0.x; d[1] = (int)v0.y; d[2] = (int)v1.x; d[3] = (int)v1.y;
    } else {
        int4 v = ((const int4*)((const int*)ei + N_EDGES))[e4];
        d[0] = v.x; d[1] = v.y; d[2] = v.z; d[3] = v.w;
    }
    #pragma unroll
    for (int i = 0; i < 4; i++) atomicAdd(&g_deg[d[i]], 1);
}

// ---------------- exclusive scan: single pass, register-blocked ----------
#define SCAN_CH 49   // 1024*49 = 50176 >= N_NODES

__global__ __launch_bounds__(1024)
void scan_kernel() {
    __shared__ int wsum[32];
    int t = threadIdx.x, lane = t & 31, w = t >> 5;
    int base = t * SCAN_CH;

    int sum = 0;
    #pragma unroll 4
    for (int i = 0; i < SCAN_CH; i++) {
        int idx = base + i;
        sum += (idx < N_NODES) ? g_deg[idx] : 0;
    }
    int incl = sum;
    #pragma unroll
    for (int off = 1; off < 32; off <<= 1) {
        int nb = __shfl_up_sync(0xffffffffu, incl, off);
        if (lane >= off) incl += nb;
    }
    if (lane == 31) wsum[w] = incl;
    __syncthreads();
    if (w == 0) {
        int ws = wsum[lane];
        #pragma unroll
        for (int off = 1; off < 32; off <<= 1) {
            int nb = __shfl_up_sync(0xffffffffu, ws, off);
            if (lane >= off) ws += nb;
        }
        wsum[lane] = ws;
    }
    __syncthreads();
    int run = incl - sum + (w ? wsum[w - 1] : 0);   // exclusive prefix of this chunk

    for (int i = 0; i < SCAN_CH; i++) {
        int idx = base + i;
        if (idx < N_NODES) {
            int v = g_deg[idx];
            g_cursor[idx] = run;
            run += v;
            g_ptr[idx + 1] = run;
        }
    }
    if (t == 0) g_ptr[0] = 0;
}

// ---------------- CSR fill: 4 edges / thread ----------------
__global__ void scatter_kernel(const void* __restrict__ ei) {
    int e4 = blockIdx.x * blockDim.x + threadIdx.x;
    if (e4 * 4 >= N_EDGES) return;
    int s[4], d[4];
    if (g_is64) {
        const longlong2* ps = (const longlong2*)ei + e4 * 2;
        const longlong2* pd = (const longlong2*)((const long long*)ei + N_EDGES) + e4 * 2;
        longlong2 s0 = ps[0], s1 = ps[1], d0 = pd[0], d1 = pd[1];
        s[0] = (int)s0.x; s[1] = (int)s0.y; s[2] = (int)s1.x; s[3] = (int)s1.y;
        d[0] = (int)d0.x; d[1] = (int)d0.y; d[2] = (int)d1.x; d[3] = (int)d1.y;
    } else {
        int4 vs = ((const int4*)ei)[e4];
        int4 vd = ((const int4*)((const int*)ei + N_EDGES))[e4];
        s[0] = vs.x; s[1] = vs.y; s[2] = vs.z; s[3] = vs.w;
        d[0] = vd.x; d[1] = vd.y; d[2] = vd.z; d[3] = vd.w;
    }
    #pragma unroll
    for (int i = 0; i < 4; i++) {
        int pos = atomicAdd(&g_cursor[d[i]], 1);
        g_csr_src[pos] = s[i];
    }
}

// ---------------- aggregation: 128 threads/node, half2 channels ----------
__global__ __launch_bounds__(128)
void agg_kernel(float* __restrict__ out) {
    __shared__ float s_w[32][8];
    __shared__ int   s_src[32];

    int n = blockIdx.x;
    int t = threadIdx.x;        // channel pair: 2t, 2t+1
    int h = t >> 4;

    float ss = g_eL[n * HEADS + h] + g_eR[n * HEADS + h];
    ss = fmaxf(ss, NEG_SLOPE * ss);
    float wself = __expf(ss);

    float2 whs = __half22float2(g_Whh[(size_t)n * (HC / 2) + t]);
    float2 acc = make_float2(wself * whs.x, wself * whs.y);
    float denom = wself;

    int beg = g_ptr[n];
    int end = g_ptr[n + 1];

    int eh   = t & 7;
    int eidx = t >> 3;          // 0..15
    float er_h = g_eR[n * HEADS + eh];

    for (int base = beg; base < end; base += 32) {
        int cnt = min(32, end - base);
        __syncthreads();
        #pragma unroll
        for (int j = eidx; j < 32; j += 16) {
            if (j < cnt) {
                int src = g_csr_src[base + j];
                if (eh == 0) s_src[j] = src;
                float s = g_eL[src * HEADS + eh] + er_h;
                s = fmaxf(s, NEG_SLOPE * s);
                s_w[j][eh] = __expf(s);
            }
        }
        __syncthreads();
        #pragma unroll 2
        for (int k = 0; k < cnt; k++) {
            int src = s_src[k];
            float w = s_w[k][h];
            float2 v = __half22float2(g_Whh[(size_t)src * (HC / 2) + t]);
            acc.x = fmaf(w, v.x, acc.x);
            acc.y = fmaf(w, v.y, acc.y);
            denom += w;
        }
    }
    float inv = 1.0f / (denom + 1e-16f);
    *(float2*)&out[(size_t)n * HC + 2 * t] = make_float2(acc.x * inv, acc.y * inv);
}

// ---------------- launch ----------------
extern "C" void kernel_launch(void* const* d_in, const int* in_sizes, int n_in,
                              void* d_out, int out_size) {
    const float* x  = (const float*)d_in[0];
    const void*  ei = d_in[1];
    const float* W  = (const float*)d_in[2];
    const float* aL = (const float*)d_in[3];
    const float* aR = (const float*)d_in[4];
    float* out = (float*)d_out;

    init_kernel<<<(N_NODES + 255) / 256, 256>>>((const int*)ei);

    dim3 ggrid((N_NODES + 127) / 128, HC / 64);
    gemm_kernel<<<ggrid, 256>>>(x, W, aL, aR);

    deg_kernel<<<(N_EDGES / 4 + 255) / 256, 256>>>(ei);
    scan_kernel<<<1, 1024>>>();
    scatter_kernel<<<(N_EDGES / 4 + 255) / 256, 256>>>(ei);
    agg_kernel<<<N_NODES, 128>>>(out);
}

// round 4
// speedup vs baseline: 2.0739x; 1.2978x over previous
#include <cuda_runtime.h>
#include <cuda_bf16.h>
#include <cuda_fp16.h>
#include <cstdint>

// ---------------- problem constants ----------------
#define N_NODES   50000
#define N_EDGES   800000
#define IN_CH     256
#define HEADS     8
#define OUT_CH    32
#define HC        256          // HEADS*OUT_CH
#define NEG_SLOPE 0.2f

#define SCAN_CHUNK  512
#define SCAN_BLOCKS ((N_NODES + SCAN_CHUNK - 1) / SCAN_CHUNK)   // 98

// ---------------- device scratch ----------------
__device__ __half2 g_Whh[(size_t)N_NODES * (HC / 2)];   // 25.6 MB, fp16 Wh
__device__ float g_eL[N_NODES * HEADS];
__device__ float g_eR[N_NODES * HEADS];
__device__ int   g_deg[N_NODES];
__device__ int   g_ptr[N_NODES + 1];
__device__ int   g_cursor[N_NODES];
__device__ int   g_csr_src[N_EDGES];
__device__ int   g_blocksum[SCAN_BLOCKS];
__device__ int   g_blockoff[SCAN_BLOCKS];
__device__ int   g_is64;

// ---------------- init: dtype detect + zero deg ----------------
__global__ void init_kernel(const int* ei_words) {
    int i = blockIdx.x * blockDim.x + threadIdx.x;
    if (i == 0) {
        int all0 = 1;
        for (int k = 0; k < 64; k++) {
            if (ei_words[2 * k + 1] != 0) { all0 = 0; break; }
        }
        g_is64 = all0;
    }
    if (i < N_NODES) g_deg[i] = 0;
}

// ---------------- bf16 split helper ----------------
__device__ __forceinline__ uint32_t pack_split(float x0, float x1, uint32_t& lo_out) {
    __nv_bfloat16 h0 = __float2bfloat16_rn(x0);
    __nv_bfloat16 h1 = __float2bfloat16_rn(x1);
    __nv_bfloat16 l0 = __float2bfloat16_rn(x0 - __bfloat162float(h0));
    __nv_bfloat16 l1 = __float2bfloat16_rn(x1 - __bfloat162float(h1));
    lo_out = (uint32_t)__bfloat16_as_ushort(l0) | ((uint32_t)__bfloat16_as_ushort(l1) << 16);
    return (uint32_t)__bfloat16_as_ushort(h0) | ((uint32_t)__bfloat16_as_ushort(h1) << 16);
}

__device__ __forceinline__ void mma_bf16(float* c, const uint32_t* a, const uint32_t* b) {
    asm volatile(
        "mma.sync.aligned.m16n8k16.row.col.f32.bf16.bf16.f32 "
        "{%0,%1,%2,%3}, {%4,%5,%6,%7}, {%8,%9}, {%0,%1,%2,%3};\n"
        : "+f"(c[0]), "+f"(c[1]), "+f"(c[2]), "+f"(c[3])
        : "r"(a[0]), "r"(a[1]), "r"(a[2]), "r"(a[3]), "r"(b[0]), "r"(b[1]));
}

// ---------------- GEMM: Wh = x @ W^T  (tensor cores, bf16x3 split) --------
#define SA 20   // smem row stride in bf16-pairs

__global__ __launch_bounds__(256, 2)
void gemm_kernel(const float* __restrict__ x, const float* __restrict__ W,
                 const float* __restrict__ aL, const float* __restrict__ aR) {
    __shared__ uint32_t Ah[128 * SA], Al[128 * SA];
    __shared__ uint32_t Bh[64 * SA],  Bl[64 * SA];

    const int t    = threadIdx.x;
    const int m0   = blockIdx.x * 128;
    const int n0   = blockIdx.y * 64;
    const int wid  = t >> 5, lane = t & 31;
    const int wm   = wid & 3, wn = wid >> 2;
    const int g    = lane >> 2, tt = lane & 3;

    const int ar = t >> 1;
    const int ak = (t & 1) * 16;
    const int br = t >> 2;
    const int bk = (t & 3) * 8;

    float c[2][4][4];
    #pragma unroll
    for (int i = 0; i < 2; i++)
        #pragma unroll
        for (int j = 0; j < 4; j++)
            #pragma unroll
            for (int k = 0; k < 4; k++) c[i][j][k] = 0.0f;

    float4 a_reg[4];
    float4 b_reg[2];

    auto loadA = [&](int k0) {
        int m = m0 + ar;
        if (m < N_NODES) {
            const float4* p = (const float4*)(x + (size_t)m * IN_CH + k0 + ak);
            a_reg[0] = p[0]; a_reg[1] = p[1]; a_reg[2] = p[2]; a_reg[3] = p[3];
        } else {
            a_reg[0] = a_reg[1] = a_reg[2] = a_reg[3] = make_float4(0.f, 0.f, 0.f, 0.f);
        }
        const float4* q = (const float4*)(W + (size_t)(n0 + br) * IN_CH + k0 + bk);
        b_reg[0] = q[0]; b_reg[1] = q[1];
    };

    loadA(0);

    for (int k0 = 0; k0 < IN_CH; k0 += 32) {
        {
            float av[16] = {a_reg[0].x, a_reg[0].y, a_reg[0].z, a_reg[0].w,
                            a_reg[1].x, a_reg[1].y, a_reg[1].z, a_reg[1].w,
                            a_reg[2].x, a_reg[2].y, a_reg[2].z, a_reg[2].w,
                            a_reg[3].x, a_reg[3].y, a_reg[3].z, a_reg[3].w};
            #pragma unroll
            for (int i = 0; i < 8; i++) {
                uint32_t lo;
                uint32_t hi = pack_split(av[2 * i], av[2 * i + 1], lo);
                Ah[ar * SA + ak / 2 + i] = hi;
                Al[ar * SA + ak / 2 + i] = lo;
            }
            float bv[8] = {b_reg[0].x, b_reg[0].y, b_reg[0].z, b_reg[0].w,
                           b_reg[1].x, b_reg[1].y, b_reg[1].z, b_reg[1].w};
            #pragma unroll
            for (int i = 0; i < 4; i++) {
                uint32_t lo;
                uint32_t hi = pack_split(bv[2 * i], bv[2 * i + 1], lo);
                Bh[br * SA + bk / 2 + i] = hi;
                Bl[br * SA + bk / 2 + i] = lo;
            }
        }
        __syncthreads();

        if (k0 + 32 < IN_CH) loadA(k0 + 32);

        #pragma unroll
        for (int ks = 0; ks < 2; ks++) {
            const int kb2 = ks * 8;
            uint32_t bhf[4][2], blf[4][2];
            #pragma unroll
            for (int fn = 0; fn < 4; fn++) {
                int nrow = wn * 32 + fn * 8 + g;
                bhf[fn][0] = Bh[nrow * SA + kb2 + tt];
                bhf[fn][1] = Bh[nrow * SA + kb2 + 4 + tt];
                blf[fn][0] = Bl[nrow * SA + kb2 + tt];
                blf[fn][1] = Bl[nrow * SA + kb2 + 4 + tt];
            }
            #pragma unroll
            for (int fm = 0; fm < 2; fm++) {
                int r0 = wm * 32 + fm * 16 + g;
                uint32_t ahf[4], alf[4];
                ahf[0] = Ah[r0 * SA + kb2 + tt];
                ahf[1] = Ah[(r0 + 8) * SA + kb2 + tt];
                ahf[2] = Ah[r0 * SA + kb2 + 4 + tt];
                ahf[3] = Ah[(r0 + 8) * SA + kb2 + 4 + tt];
                alf[0] = Al[r0 * SA + kb2 + tt];
                alf[1] = Al[(r0 + 8) * SA + kb2 + tt];
                alf[2] = Al[r0 * SA + kb2 + 4 + tt];
                alf[3] = Al[(r0 + 8) * SA + kb2 + 4 + tt];
                #pragma unroll
                for (int fn = 0; fn < 4; fn++) {
                    mma_bf16(c[fm][fn], ahf, bhf[fn]);
                    mma_bf16(c[fm][fn], ahf, blf[fn]);
                    mma_bf16(c[fm][fn], alf, bhf[fn]);
                }
            }
        }
        __syncthreads();
    }

    // ---- epilogue: store fp16 Wh + fused eL/eR ----
    const int h = blockIdx.y * 2 + wn;
    float aLv[8], aRv[8];
    #pragma unroll
    for (int fn = 0; fn < 4; fn++) {
        int c0 = fn * 8 + 2 * tt;
        aLv[2 * fn]     = aL[h * 32 + c0];
        aLv[2 * fn + 1] = aL[h * 32 + c0 + 1];
        aRv[2 * fn]     = aR[h * 32 + c0];
        aRv[2 * fn + 1] = aR[h * 32 + c0 + 1];
    }

    #pragma unroll
    for (int fm = 0; fm < 2; fm++) {
        int mrow = m0 + wm * 32 + fm * 16 + g;
        #pragma unroll
        for (int fn = 0; fn < 4; fn++) {
            int colp = (n0 + wn * 32 + fn * 8 + 2 * tt) >> 1;
            if (mrow < N_NODES)
                g_Whh[(size_t)mrow * (HC / 2) + colp] =
                    __floats2half2_rn(c[fm][fn][0], c[fm][fn][1]);
            if (mrow + 8 < N_NODES)
                g_Whh[(size_t)(mrow + 8) * (HC / 2) + colp] =
                    __floats2half2_rn(c[fm][fn][2], c[fm][fn][3]);
        }
        #pragma unroll
        for (int half = 0; half < 2; half++) {
            float pl = 0.f, pr = 0.f;
            #pragma unroll
            for (int fn = 0; fn < 4; fn++) {
                pl += c[fm][fn][2 * half] * aLv[2 * fn] + c[fm][fn][2 * half + 1] * aLv[2 * fn + 1];
                pr += c[fm][fn][2 * half] * aRv[2 * fn] + c[fm][fn][2 * half + 1] * aRv[2 * fn + 1];
            }
            pl += __shfl_xor_sync(0xffffffffu, pl, 1);
            pl += __shfl_xor_sync(0xffffffffu, pl, 2);
            pr += __shfl_xor_sync(0xffffffffu, pr, 1);
            pr += __shfl_xor_sync(0xffffffffu, pr, 2);
            int m = mrow + half * 8;
            if (tt == 0 && m < N_NODES) {
                g_eL[m * HEADS + h] = pl;
                g_eR[m * HEADS + h] = pr;
            }
        }
    }
}

// ---------------- degree count: 4 edges / thread ----------------
__global__ void deg_kernel(const void* __restrict__ ei) {
    int e4 = blockIdx.x * blockDim.x + threadIdx.x;
    if (e4 * 4 >= N_EDGES) return;
    int d[4];
    if (g_is64) {
        const longlong2* p = (const longlong2*)((const long long*)ei + N_EDGES) + e4 * 2;
        longlong2 v0 = p[0], v1 = p[1];
        d[0] = (int)v0.x; d[1] = (int)v0.y; d[2] = (int)v1.x; d[3] = (int)v1.y;
    } else {
        int4 v = ((const int4*)((const int*)ei + N_EDGES))[e4];
        d[0] = v.x; d[1] = v.y; d[2] = v.z; d[3] = v.w;
    }
    #pragma unroll
    for (int i = 0; i < 4; i++) atomicAdd(&g_deg[d[i]], 1);
}

// ---------------- scan phase 1: per-block sums (98 blocks x 512) ----------
__global__ __launch_bounds__(SCAN_CHUNK)
void scan1_kernel() {
    __shared__ int wsum[SCAN_CHUNK / 32];
    int t = threadIdx.x, lane = t & 31, w = t >> 5;
    int idx = blockIdx.x * SCAN_CHUNK + t;
    int v = (idx < N_NODES) ? g_deg[idx] : 0;
    #pragma unroll
    for (int off = 16; off > 0; off >>= 1) v += __shfl_down_sync(0xffffffffu, v, off);
    if (lane == 0) wsum[w] = v;
    __syncthreads();
    if (t < SCAN_CHUNK / 32) {
        int s = wsum[t];
        #pragma unroll
        for (int off = 8; off > 0; off >>= 1) s += __shfl_down_sync(0xffffu, s, off);
        if (t == 0) g_blocksum[blockIdx.x] = s;
    }
}

// ---------------- scan phase 2: scan the 98 block sums (1 block) ----------
__global__ __launch_bounds__(128)
void scan2_kernel() {
    __shared__ int wsum[4];
    int t = threadIdx.x, lane = t & 31, w = t >> 5;
    int v = (t < SCAN_BLOCKS) ? g_blocksum[t] : 0;
    int incl = v;
    #pragma unroll
    for (int off = 1; off < 32; off <<= 1) {
        int nb = __shfl_up_sync(0xffffffffu, incl, off);
        if (lane >= off) incl += nb;
    }
    if (lane == 31) wsum[w] = incl;
    __syncthreads();
    if (w == 0 && lane < 4) {
        int s = wsum[lane];
        #pragma unroll
        for (int off = 1; off < 4; off <<= 1) {
            int nb = __shfl_up_sync(0xfu, s, off);
            if (lane >= off) s += nb;
        }
        wsum[lane] = s;
    }
    __syncthreads();
    int excl = incl - v + (w ? wsum[w - 1] : 0);
    if (t < SCAN_BLOCKS) g_blockoff[t] = excl;
}

// ---------------- scan phase 3: block-local exclusive scan + offset -------
__global__ __launch_bounds__(SCAN_CHUNK)
void scan3_kernel() {
    __shared__ int wsum[SCAN_CHUNK / 32];
    int t = threadIdx.x, lane = t & 31, w = t >> 5;
    int idx = blockIdx.x * SCAN_CHUNK + t;
    int v = (idx < N_NODES) ? g_deg[idx] : 0;
    int incl = v;
    #pragma unroll
    for (int off = 1; off < 32; off <<= 1) {
        int nb = __shfl_up_sync(0xffffffffu, incl, off);
        if (lane >= off) incl += nb;
    }
    if (lane == 31) wsum[w] = incl;
    __syncthreads();
    if (t < SCAN_CHUNK / 32) {
        int s = wsum[t];
        #pragma unroll
        for (int off = 1; off < SCAN_CHUNK / 32; off <<= 1) {
            int nb = __shfl_up_sync(0xffffu, s, off);
            if ((t & 15) >= off) s += nb;
        }
        wsum[t] = s;
    }
    __syncthreads();
    int boff = g_blockoff[blockIdx.x];
    int incl_tot = incl + (w ? wsum[w - 1] : 0) + boff;
    if (idx < N_NODES) {
        g_cursor[idx]   = incl_tot - v;
        g_ptr[idx + 1]  = incl_tot;
    }
    if (idx == 0) g_ptr[0] = 0;
}

// ---------------- CSR fill: 4 edges / thread ----------------
__global__ void scatter_kernel(const void* __restrict__ ei) {
    int e4 = blockIdx.x * blockDim.x + threadIdx.x;
    if (e4 * 4 >= N_EDGES) return;
    int s[4], d[4];
    if (g_is64) {
        const longlong2* ps = (const longlong2*)ei + e4 * 2;
        const longlong2* pd = (const longlong2*)((const long long*)ei + N_EDGES) + e4 * 2;
        longlong2 s0 = ps[0], s1 = ps[1], d0 = pd[0], d1 = pd[1];
        s[0] = (int)s0.x; s[1] = (int)s0.y; s[2] = (int)s1.x; s[3] = (int)s1.y;
        d[0] = (int)d0.x; d[1] = (int)d0.y; d[2] = (int)d1.x; d[3] = (int)d1.y;
    } else {
        int4 vs = ((const int4*)ei)[e4];
        int4 vd = ((const int4*)((const int*)ei + N_EDGES))[e4];
        s[0] = vs.x; s[1] = vs.y; s[2] = vs.z; s[3] = vs.w;
        d[0] = vd.x; d[1] = vd.y; d[2] = vd.z; d[3] = vd.w;
    }
    #pragma unroll
    for (int i = 0; i < 4; i++) {
        int pos = atomicAdd(&g_cursor[d[i]], 1);
        g_csr_src[pos] = s[i];
    }
}

// ---------------- aggregation: 128 threads/node, half2 channels ----------
__global__ __launch_bounds__(128)
void agg_kernel(float* __restrict__ out) {
    __shared__ float s_w[32][8];
    __shared__ int   s_src[32];

    int n = blockIdx.x;
    int t = threadIdx.x;        // channel pair: 2t, 2t+1
    int h = t >> 4;

    float ss = g_eL[n * HEADS + h] + g_eR[n * HEADS + h];
    ss = fmaxf(ss, NEG_SLOPE * ss);
    float wself = __expf(ss);

    float2 whs = __half22float2(g_Whh[(size_t)n * (HC / 2) + t]);
    float2 acc = make_float2(wself * whs.x, wself * whs.y);
    float denom = wself;

    int beg = g_ptr[n];
    int end = g_ptr[n + 1];

    int eh   = t & 7;
    int eidx = t >> 3;          // 0..15
    float er_h = g_eR[n * HEADS + eh];

    for (int base = beg; base < end; base += 32) {
        int cnt = min(32, end - base);
        __syncthreads();
        #pragma unroll
        for (int j = eidx; j < 32; j += 16) {
            if (j < cnt) {
                int src = g_csr_src[base + j];
                if (eh == 0) s_src[j] = src;
                float s = g_eL[src * HEADS + eh] + er_h;
                s = fmaxf(s, NEG_SLOPE * s);
                s_w[j][eh] = __expf(s);
            }
        }
        __syncthreads();
        #pragma unroll 2
        for (int k = 0; k < cnt; k++) {
            int src = s_src[k];
            float w = s_w[k][h];
            float2 v = __half22float2(g_Whh[(size_t)src * (HC / 2) + t]);
            acc.x = fmaf(w, v.x, acc.x);
            acc.y = fmaf(w, v.y, acc.y);
            denom += w;
        }
    }
    float inv = 1.0f / (denom + 1e-16f);
    *(float2*)&out[(size_t)n * HC + 2 * t] = make_float2(acc.x * inv, acc.y * inv);
}

// ---------------- launch ----------------
extern "C" void kernel_launch(void* const* d_in, const int* in_sizes, int n_in,
                              void* d_out, int out_size) {
    const float* x  = (const float*)d_in[0];
    const void*  ei = d_in[1];
    const float* W  = (const float*)d_in[2];
    const float* aL = (const float*)d_in[3];
    const float* aR = (const float*)d_in[4];
    float* out = (float*)d_out;

    init_kernel<<<(N_NODES + 255) / 256, 256>>>((const int*)ei);

    dim3 ggrid((N_NODES + 127) / 128, HC / 64);
    gemm_kernel<<<ggrid, 256>>>(x, W, aL, aR);

    deg_kernel<<<(N_EDGES / 4 + 255) / 256, 256>>>(ei);
    scan1_kernel<<<SCAN_BLOCKS, SCAN_CHUNK>>>();
    scan2_kernel<<<1, 128>>>();
    scan3_kernel<<<SCAN_BLOCKS, SCAN_CHUNK>>>();
    scatter_kernel<<<(N_EDGES / 4 + 255) / 256, 256>>>(ei);
    agg_kernel<<<N_NODES, 128>>>(out);
}

// round 5
// speedup vs baseline: 2.4464x; 1.1796x over previous
#include <cuda_runtime.h>
#include <cuda_bf16.h>
#include <cuda_fp16.h>
#include <cstdint>

// ---------------- problem constants ----------------
#define N_NODES   50000
#define N_EDGES   800000
#define IN_CH     256
#define HEADS     8
#define OUT_CH    32
#define HC        256          // HEADS*OUT_CH
#define NEG_SLOPE 0.2f

#define SCAN_CHUNK  512
#define SCAN_BLOCKS ((N_NODES + SCAN_CHUNK - 1) / SCAN_CHUNK)   // 98

// ---------------- device scratch ----------------
__device__ __half2 g_Whh[(size_t)N_NODES * (HC / 2)];   // 25.6 MB, fp16 Wh
__device__ float g_eL[N_NODES * HEADS];
__device__ float g_eR[N_NODES * HEADS];
__device__ int   g_deg[N_NODES];
__device__ int   g_ptr[N_NODES + 1];
__device__ int   g_cursor[N_NODES];
__device__ int   g_csr_src[N_EDGES];
__device__ int   g_blocksum[SCAN_BLOCKS];
__device__ int   g_blockoff[SCAN_BLOCKS];
__device__ int   g_is64;

// ---------------- init: dtype detect + zero deg ----------------
__global__ void init_kernel(const int* ei_words) {
    int i = blockIdx.x * blockDim.x + threadIdx.x;
    if (i == 0) {
        int all0 = 1;
        for (int k = 0; k < 64; k++) {
            if (ei_words[2 * k + 1] != 0) { all0 = 0; break; }
        }
        g_is64 = all0;
    }
    if (i < N_NODES) g_deg[i] = 0;
}

// ---------------- bf16 split helper ----------------
__device__ __forceinline__ uint32_t pack_split(float x0, float x1, uint32_t& lo_out) {
    __nv_bfloat16 h0 = __float2bfloat16_rn(x0);
    __nv_bfloat16 h1 = __float2bfloat16_rn(x1);
    __nv_bfloat16 l0 = __float2bfloat16_rn(x0 - __bfloat162float(h0));
    __nv_bfloat16 l1 = __float2bfloat16_rn(x1 - __bfloat162float(h1));
    lo_out = (uint32_t)__bfloat16_as_ushort(l0) | ((uint32_t)__bfloat16_as_ushort(l1) << 16);
    return (uint32_t)__bfloat16_as_ushort(h0) | ((uint32_t)__bfloat16_as_ushort(h1) << 16);
}

__device__ __forceinline__ void mma_bf16(float* c, const uint32_t* a, const uint32_t* b) {
    asm volatile(
        "mma.sync.aligned.m16n8k16.row.col.f32.bf16.bf16.f32 "
        "{%0,%1,%2,%3}, {%4,%5,%6,%7}, {%8,%9}, {%0,%1,%2,%3};\n"
        : "+f"(c[0]), "+f"(c[1]), "+f"(c[2]), "+f"(c[3])
        : "r"(a[0]), "r"(a[1]), "r"(a[2]), "r"(a[3]), "r"(b[0]), "r"(b[1]));
}

// ---------------- GEMM: Wh = x @ W^T  (tensor cores, bf16x3 split) --------
// Tile: BM=128, BN=128, BK=32. 8 warps (2x4). Warp tile 64x32 = one head wide.
// Fused epilogue computes eL/eR and stores Wh as fp16.
#define SA 20   // smem row stride in bf16-pairs

__global__ __launch_bounds__(256, 2)
void gemm_kernel(const float* __restrict__ x, const float* __restrict__ W,
                 const float* __restrict__ aL, const float* __restrict__ aR) {
    __shared__ uint32_t Ah[128 * SA], Al[128 * SA];
    __shared__ uint32_t Bh[128 * SA], Bl[128 * SA];

    const int t    = threadIdx.x;
    const int m0   = blockIdx.x * 128;
    const int n0   = blockIdx.y * 128;
    const int wid  = t >> 5, lane = t & 31;
    const int wm   = wid >> 2, wn = wid & 3;    // 2 x 4 warp grid
    const int g    = lane >> 2, tt = lane & 3;

    const int r  = t >> 1;             // tile row 0..127 (A and B loaders)
    const int kq = (t & 1) * 16;       // k-half

    float c[4][4][4];
    #pragma unroll
    for (int i = 0; i < 4; i++)
        #pragma unroll
        for (int j = 0; j < 4; j++)
            #pragma unroll
            for (int k = 0; k < 4; k++) c[i][j][k] = 0.0f;

    float4 a_reg[4];

    auto loadA = [&](int k0) {
        int m = m0 + r;
        if (m < N_NODES) {
            const float4* p = (const float4*)(x + (size_t)m * IN_CH + k0 + kq);
            a_reg[0] = p[0]; a_reg[1] = p[1]; a_reg[2] = p[2]; a_reg[3] = p[3];
        } else {
            a_reg[0] = a_reg[1] = a_reg[2] = a_reg[3] = make_float4(0.f, 0.f, 0.f, 0.f);
        }
    };

    loadA(0);

    for (int k0 = 0; k0 < IN_CH; k0 += 32) {
        // B tile: L2/L1 resident after first pass; load + split in place
        {
            const float4* q = (const float4*)(W + (size_t)(n0 + r) * IN_CH + k0 + kq);
            float4 b0 = q[0], b1 = q[1], b2 = q[2], b3 = q[3];
            float bv[16] = {b0.x, b0.y, b0.z, b0.w, b1.x, b1.y, b1.z, b1.w,
                            b2.x, b2.y, b2.z, b2.w, b3.x, b3.y, b3.z, b3.w};
            #pragma unroll
            for (int i = 0; i < 8; i++) {
                uint32_t lo;
                uint32_t hi = pack_split(bv[2 * i], bv[2 * i + 1], lo);
                Bh[r * SA + kq / 2 + i] = hi;
                Bl[r * SA + kq / 2 + i] = lo;
            }
        }
        // A tile from prefetched regs
        {
            float av[16] = {a_reg[0].x, a_reg[0].y, a_reg[0].z, a_reg[0].w,
                            a_reg[1].x, a_reg[1].y, a_reg[1].z, a_reg[1].w,
                            a_reg[2].x, a_reg[2].y, a_reg[2].z, a_reg[2].w,
                            a_reg[3].x, a_reg[3].y, a_reg[3].z, a_reg[3].w};
            #pragma unroll
            for (int i = 0; i < 8; i++) {
                uint32_t lo;
                uint32_t hi = pack_split(av[2 * i], av[2 * i + 1], lo);
                Ah[r * SA + kq / 2 + i] = hi;
                Al[r * SA + kq / 2 + i] = lo;
            }
        }
        __syncthreads();

        if (k0 + 32 < IN_CH) loadA(k0 + 32);   // prefetch next A

        #pragma unroll
        for (int ks = 0; ks < 2; ks++) {
            const int kb2 = ks * 8;
            uint32_t bhf[4][2], blf[4][2];
            #pragma unroll
            for (int fn = 0; fn < 4; fn++) {
                int nrow = wn * 32 + fn * 8 + g;
                bhf[fn][0] = Bh[nrow * SA + kb2 + tt];
                bhf[fn][1] = Bh[nrow * SA + kb2 + 4 + tt];
                blf[fn][0] = Bl[nrow * SA + kb2 + tt];
                blf[fn][1] = Bl[nrow * SA + kb2 + 4 + tt];
            }
            #pragma unroll
            for (int fm = 0; fm < 4; fm++) {
                int r0 = wm * 64 + fm * 16 + g;
                uint32_t ahf[4], alf[4];
                ahf[0] = Ah[r0 * SA + kb2 + tt];
                ahf[1] = Ah[(r0 + 8) * SA + kb2 + tt];
                ahf[2] = Ah[r0 * SA + kb2 + 4 + tt];
                ahf[3] = Ah[(r0 + 8) * SA + kb2 + 4 + tt];
                alf[0] = Al[r0 * SA + kb2 + tt];
                alf[1] = Al[(r0 + 8) * SA + kb2 + tt];
                alf[2] = Al[r0 * SA + kb2 + 4 + tt];
                alf[3] = Al[(r0 + 8) * SA + kb2 + 4 + tt];
                #pragma unroll
                for (int fn = 0; fn < 4; fn++) {
                    mma_bf16(c[fm][fn], ahf, bhf[fn]);   // hi*hi
                    mma_bf16(c[fm][fn], ahf, blf[fn]);   // hi*lo
                    mma_bf16(c[fm][fn], alf, bhf[fn]);   // lo*hi
                }
            }
        }
        __syncthreads();
    }

    // ---- epilogue: store fp16 Wh + fused eL/eR ----
    const int h = blockIdx.y * 4 + wn;   // global head for this warp
    float aLv[8], aRv[8];
    #pragma unroll
    for (int fn = 0; fn < 4; fn++) {
        int c0 = fn * 8 + 2 * tt;
        aLv[2 * fn]     = aL[h * 32 + c0];
        aLv[2 * fn + 1] = aL[h * 32 + c0 + 1];
        aRv[2 * fn]     = aR[h * 32 + c0];
        aRv[2 * fn + 1] = aR[h * 32 + c0 + 1];
    }

    #pragma unroll
    for (int fm = 0; fm < 4; fm++) {
        int mrow = m0 + wm * 64 + fm * 16 + g;
        #pragma unroll
        for (int fn = 0; fn < 4; fn++) {
            int colp = (n0 + wn * 32 + fn * 8 + 2 * tt) >> 1;  // half2 index
            if (mrow < N_NODES)
                g_Whh[(size_t)mrow * (HC / 2) + colp] =
                    __floats2half2_rn(c[fm][fn][0], c[fm][fn][1]);
            if (mrow + 8 < N_NODES)
                g_Whh[(size_t)(mrow + 8) * (HC / 2) + colp] =
                    __floats2half2_rn(c[fm][fn][2], c[fm][fn][3]);
        }
        #pragma unroll
        for (int half = 0; half < 2; half++) {
            float pl = 0.f, pr = 0.f;
            #pragma unroll
            for (int fn = 0; fn < 4; fn++) {
                pl += c[fm][fn][2 * half] * aLv[2 * fn] + c[fm][fn][2 * half + 1] * aLv[2 * fn + 1];
                pr += c[fm][fn][2 * half] * aRv[2 * fn] + c[fm][fn][2 * half + 1] * aRv[2 * fn + 1];
            }
            pl += __shfl_xor_sync(0xffffffffu, pl, 1);
            pl += __shfl_xor_sync(0xffffffffu, pl, 2);
            pr += __shfl_xor_sync(0xffffffffu, pr, 1);
            pr += __shfl_xor_sync(0xffffffffu, pr, 2);
            int m = mrow + half * 8;
            if (tt == 0 && m < N_NODES) {
                g_eL[m * HEADS + h] = pl;
                g_eR[m * HEADS + h] = pr;
            }
        }
    }
}

// ---------------- degree count: 4 edges / thread ----------------
__global__ void deg_kernel(const void* __restrict__ ei) {
    int e4 = blockIdx.x * blockDim.x + threadIdx.x;
    if (e4 * 4 >= N_EDGES) return;
    int d[4];
    if (g_is64) {
        const longlong2* p = (const longlong2*)((const long long*)ei + N_EDGES) + e4 * 2;
        longlong2 v0 = p[0], v1 = p[1];
        d[0] = (int)v0.x; d[1] = (int)v0.y; d[2] = (int)v1.x; d[3] = (int)v1.y;
    } else {
        int4 v = ((const int4*)((const int*)ei + N_EDGES))[e4];
        d[0] = v.x; d[1] = v.y; d[2] = v.z; d[3] = v.w;
    }
    #pragma unroll
    for (int i = 0; i < 4; i++) atomicAdd(&g_deg[d[i]], 1);
}

// ---------------- scan phase 1: per-block sums ----------
__global__ __launch_bounds__(SCAN_CHUNK)
void scan1_kernel() {
    __shared__ int wsum[SCAN_CHUNK / 32];
    int t = threadIdx.x, lane = t & 31, w = t >> 5;
    int idx = blockIdx.x * SCAN_CHUNK + t;
    int v = (idx < N_NODES) ? g_deg[idx] : 0;
    #pragma unroll
    for (int off = 16; off > 0; off >>= 1) v += __shfl_down_sync(0xffffffffu, v, off);
    if (lane == 0) wsum[w] = v;
    __syncthreads();
    if (t < SCAN_CHUNK / 32) {
        int s = wsum[t];
        #pragma unroll
        for (int off = 8; off > 0; off >>= 1) s += __shfl_down_sync(0xffffu, s, off);
        if (t == 0) g_blocksum[blockIdx.x] = s;
    }
}

// ---------------- scan phase 2: scan block sums ----------
__global__ __launch_bounds__(128)
void scan2_kernel() {
    __shared__ int wsum[4];
    int t = threadIdx.x, lane = t & 31, w = t >> 5;
    int v = (t < SCAN_BLOCKS) ? g_blocksum[t] : 0;
    int incl = v;
    #pragma unroll
    for (int off = 1; off < 32; off <<= 1) {
        int nb = __shfl_up_sync(0xffffffffu, incl, off);
        if (lane >= off) incl += nb;
    }
    if (lane == 31) wsum[w] = incl;
    __syncthreads();
    if (w == 0 && lane < 4) {
        int s = wsum[lane];
        #pragma unroll
        for (int off = 1; off < 4; off <<= 1) {
            int nb = __shfl_up_sync(0xfu, s, off);
            if (lane >= off) s += nb;
        }
        wsum[lane] = s;
    }
    __syncthreads();
    int excl = incl - v + (w ? wsum[w - 1] : 0);
    if (t < SCAN_BLOCKS) g_blockoff[t] = excl;
}

// ---------------- scan phase 3: block-local exclusive scan + offset -------
__global__ __launch_bounds__(SCAN_CHUNK)
void scan3_kernel() {
    __shared__ int wsum[SCAN_CHUNK / 32];
    int t = threadIdx.x, lane = t & 31, w = t >> 5;
    int idx = blockIdx.x * SCAN_CHUNK + t;
    int v = (idx < N_NODES) ? g_deg[idx] : 0;
    int incl = v;
    #pragma unroll
    for (int off = 1; off < 32; off <<= 1) {
        int nb = __shfl_up_sync(0xffffffffu, incl, off);
        if (lane >= off) incl += nb;
    }
    if (lane == 31) wsum[w] = incl;
    __syncthreads();
    if (t < SCAN_CHUNK / 32) {
        int s = wsum[t];
        #pragma unroll
        for (int off = 1; off < SCAN_CHUNK / 32; off <<= 1) {
            int nb = __shfl_up_sync(0xffffu, s, off);
            if ((t & 15) >= off) s += nb;
        }
        wsum[t] = s;
    }
    __syncthreads();
    int boff = g_blockoff[blockIdx.x];
    int incl_tot = incl + (w ? wsum[w - 1] : 0) + boff;
    if (idx < N_NODES) {
        g_cursor[idx]   = incl_tot - v;
        g_ptr[idx + 1]  = incl_tot;
    }
    if (idx == 0) g_ptr[0] = 0;
}

// ---------------- CSR fill: 4 edges / thread ----------------
__global__ void scatter_kernel(const void* __restrict__ ei) {
    int e4 = blockIdx.x * blockDim.x + threadIdx.x;
    if (e4 * 4 >= N_EDGES) return;
    int s[4], d[4];
    if (g_is64) {
        const longlong2* ps = (const longlong2*)ei + e4 * 2;
        const longlong2* pd = (const longlong2*)((const long long*)ei + N_EDGES) + e4 * 2;
        longlong2 s0 = ps[0], s1 = ps[1], d0 = pd[0], d1 = pd[1];
        s[0] = (int)s0.x; s[1] = (int)s0.y; s[2] = (int)s1.x; s[3] = (int)s1.y;
        d[0] = (int)d0.x; d[1] = (int)d0.y; d[2] = (int)d1.x; d[3] = (int)d1.y;
    } else {
        int4 vs = ((const int4*)ei)[e4];
        int4 vd = ((const int4*)((const int*)ei + N_EDGES))[e4];
        s[0] = vs.x; s[1] = vs.y; s[2] = vs.z; s[3] = vs.w;
        d[0] = vd.x; d[1] = vd.y; d[2] = vd.z; d[3] = vd.w;
    }
    #pragma unroll
    for (int i = 0; i < 4; i++) {
        int pos = atomicAdd(&g_cursor[d[i]], 1);
        g_csr_src[pos] = s[i];
    }
}

// ---------------- aggregation: warp-per-node, lane = 8 channels ----------
__device__ __forceinline__ void fma_row(float* acc, float w, uint4 v) {
    float2 f0 = __half22float2(*reinterpret_cast<const __half2*>(&v.x));
    float2 f1 = __half22float2(*reinterpret_cast<const __half2*>(&v.y));
    float2 f2 = __half22float2(*reinterpret_cast<const __half2*>(&v.z));
    float2 f3 = __half22float2(*reinterpret_cast<const __half2*>(&v.w));
    acc[0] = fmaf(w, f0.x, acc[0]); acc[1] = fmaf(w, f0.y, acc[1]);
    acc[2] = fmaf(w, f1.x, acc[2]); acc[3] = fmaf(w, f1.y, acc[3]);
    acc[4] = fmaf(w, f2.x, acc[4]); acc[5] = fmaf(w, f2.y, acc[5]);
    acc[6] = fmaf(w, f3.x, acc[6]); acc[7] = fmaf(w, f3.y, acc[7]);
}

__global__ __launch_bounds__(256)
void agg_kernel(float* __restrict__ out) {
    const int lane = threadIdx.x & 31;
    const int n = blockIdx.x * 8 + (threadIdx.x >> 5);
    if (n >= N_NODES) return;

    const int h8 = lane & 7;                    // head this lane evaluates weights for
    const float er8 = g_eR[n * HEADS + h8];

    // self weight (computed redundantly in all lanes, broadcast to channel-head)
    float s0 = g_eL[n * HEADS + h8] + er8;
    s0 = fmaxf(s0, NEG_SLOPE * s0);
    float wsl = __expf(s0);
    float wself = __shfl_sync(0xffffffffu, wsl, lane >> 2);

    float acc[8];
    {
        uint4 v = ((const uint4*)&g_Whh[(size_t)n * (HC / 2)])[lane];
        float2 f0 = __half22float2(*reinterpret_cast<const __half2*>(&v.x));
        float2 f1 = __half22float2(*reinterpret_cast<const __half2*>(&v.y));
        float2 f2 = __half22float2(*reinterpret_cast<const __half2*>(&v.z));
        float2 f3 = __half22float2(*reinterpret_cast<const __half2*>(&v.w));
        acc[0] = wself * f0.x; acc[1] = wself * f0.y;
        acc[2] = wself * f1.x; acc[3] = wself * f1.y;
        acc[4] = wself * f2.x; acc[5] = wself * f2.y;
        acc[6] = wself * f3.x; acc[7] = wself * f3.y;
    }
    float denom = wself;

    const int beg = g_ptr[n];
    const int end = g_ptr[n + 1];

    for (int base = beg; base < end; base += 32) {
        int cnt = min(32, end - base);
        int src_l = (lane < cnt) ? g_csr_src[base + lane] : 0;

        for (int j = 0; j < cnt; j += 4) {
            // weights for edges j..j+3: lane = e4*8 + h8
            int e = j + (lane >> 3);
            int src_e = __shfl_sync(0xffffffffu, src_l, e & 31);
            float wv = 0.0f;
            if (e < cnt) {
                float s = g_eL[src_e * HEADS + h8] + er8;
                s = fmaxf(s, NEG_SLOPE * s);
                wv = __expf(s);
            }
            if (j + 4 <= cnt) {
                #pragma unroll
                for (int k = 0; k < 4; k++) {
                    int srck = __shfl_sync(0xffffffffu, src_l, j + k);
                    float w  = __shfl_sync(0xffffffffu, wv, (k << 3) | (lane >> 2));
                    uint4 v  = ((const uint4*)&g_Whh[(size_t)srck * (HC / 2)])[lane];
                    fma_row(acc, w, v);
                    denom += w;
                }
            } else {
                for (int k = 0; k < cnt - j; k++) {
                    int srck = __shfl_sync(0xffffffffu, src_l, j + k);
                    float w  = __shfl_sync(0xffffffffu, wv, (k << 3) | (lane >> 2));
                    uint4 v  = ((const uint4*)&g_Whh[(size_t)srck * (HC / 2)])[lane];
                    fma_row(acc, w, v);
                    denom += w;
                }
            }
        }
    }

    float inv = 1.0f / (denom + 1e-16f);
    float* op = out + (size_t)n * HC + lane * 8;
    *(float4*)op       = make_float4(acc[0] * inv, acc[1] * inv, acc[2] * inv, acc[3] * inv);
    *(float4*)(op + 4) = make_float4(acc[4] * inv, acc[5] * inv, acc[6] * inv, acc[7] * inv);
}

// ---------------- launch ----------------
extern "C" void kernel_launch(void* const* d_in, const int* in_sizes, int n_in,
                              void* d_out, int out_size) {
    const float* x  = (const float*)d_in[0];
    const void*  ei = d_in[1];
    const float* W  = (const float*)d_in[2];
    const float* aL = (const float*)d_in[3];
    const float* aR = (const float*)d_in[4];
    float* out = (float*)d_out;

    init_kernel<<<(N_NODES + 255) / 256, 256>>>((const int*)ei);

    dim3 ggrid((N_NODES + 127) / 128, HC / 128);
    gemm_kernel<<<ggrid, 256>>>(x, W, aL, aR);

    deg_kernel<<<(N_EDGES / 4 + 255) / 256, 256>>>(ei);
    scan1_kernel<<<SCAN_BLOCKS, SCAN_CHUNK>>>();
    scan2_kernel<<<1, 128>>>();
    scan3_kernel<<<SCAN_BLOCKS, SCAN_CHUNK>>>();
    scatter_kernel<<<(N_EDGES / 4 + 255) / 256, 256>>>(ei);
    agg_kernel<<<(N_NODES + 7) / 8, 256>>>(out);
}